// round 1
// baseline (speedup 1.0000x reference)
#include <cuda_runtime.h>
#include <cstdint>

// Sparsemax (faithful-to-buggy-reference variant): per row of K=2048 along the
// contiguous last axis:
//   right = inclusive cumsum(z)
//   unmasked_k : (1 + k*z_k) > right_k   (1-indexed k)
//   kmax = max unmasked k ; tmax = max unmasked right_k
//   tau = (tmax - 1) / kmax ;  out = max(0, z - tau)
// One CTA per row. 512 threads x float4 = 2048 elems. Single read + single
// write per element; everything else in registers/shuffles.

constexpr int K       = 2048;
constexpr int THREADS = 512;
constexpr int VEC     = 4;
constexpr int NWARPS  = THREADS / 32;   // 16

__global__ __launch_bounds__(THREADS, 2)
void sparsemax_rowwise_kernel(const float* __restrict__ x, float* __restrict__ y)
{
    const int row  = blockIdx.x;
    const int tid  = threadIdx.x;
    const int lane = tid & 31;
    const int wid  = tid >> 5;

    const float4* __restrict__ xin =
        reinterpret_cast<const float4*>(x + (size_t)row * K);
    float4 v = xin[tid];

    const float z0 = v.x, z1 = v.y, z2 = v.z, z3 = v.w;

    // Thread-local inclusive prefix of the 4 elements
    const float s0 = z0;
    const float s1 = s0 + z1;
    const float s2 = s1 + z2;
    const float s3 = s2 + z3;

    // Warp-level inclusive scan of per-thread sums
    float sc = s3;
    #pragma unroll
    for (int o = 1; o < 32; o <<= 1) {
        float t = __shfl_up_sync(0xffffffffu, sc, o);
        if (lane >= o) sc += t;
    }

    __shared__ float wsum[NWARPS];
    __shared__ float wkmax[NWARPS];
    __shared__ float wtmax[NWARPS];

    if (lane == 31) wsum[wid] = sc;
    __syncthreads();

    // Cross-warp exclusive offset (16 broadcast smem reads, cheap)
    float woff = 0.0f;
    #pragma unroll
    for (int i = 0; i < NWARPS; i++) {
        float t = wsum[i];
        if (i < wid) woff += t;
    }

    // Exclusive prefix for this thread's first element
    const float base = woff + (sc - s3);
    const float r0 = base + s0;
    const float r1 = base + s1;
    const float r2 = base + s2;
    const float r3 = base + s3;

    // Per-element mask + running maxes. k is 1-indexed: k = tid*4 + i + 1.
    const float kb = (float)(tid * VEC);
    float kmax = 0.0f;
    float tmax = -INFINITY;

    { const float kk = kb + 1.0f;
      if (1.0f + kk * z0 > r0) { kmax = fmaxf(kmax, kk); tmax = fmaxf(tmax, r0); } }
    { const float kk = kb + 2.0f;
      if (1.0f + kk * z1 > r1) { kmax = fmaxf(kmax, kk); tmax = fmaxf(tmax, r1); } }
    { const float kk = kb + 3.0f;
      if (1.0f + kk * z2 > r2) { kmax = fmaxf(kmax, kk); tmax = fmaxf(tmax, r2); } }
    { const float kk = kb + 4.0f;
      if (1.0f + kk * z3 > r3) { kmax = fmaxf(kmax, kk); tmax = fmaxf(tmax, r3); } }

    // Warp max reductions (both values)
    #pragma unroll
    for (int o = 16; o >= 1; o >>= 1) {
        kmax = fmaxf(kmax, __shfl_xor_sync(0xffffffffu, kmax, o));
        tmax = fmaxf(tmax, __shfl_xor_sync(0xffffffffu, tmax, o));
    }
    if (lane == 0) { wkmax[wid] = kmax; wtmax[wid] = tmax; }
    __syncthreads();

    float km = 0.0f, tm = -INFINITY;
    #pragma unroll
    for (int i = 0; i < NWARPS; i++) {
        km = fmaxf(km, wkmax[i]);
        tm = fmaxf(tm, wtmax[i]);
    }

    const float tau = (tm - 1.0f) / km;

    float4 o4;
    o4.x = fmaxf(0.0f, z0 - tau);
    o4.y = fmaxf(0.0f, z1 - tau);
    o4.z = fmaxf(0.0f, z2 - tau);
    o4.w = fmaxf(0.0f, z3 - tau);
    reinterpret_cast<float4*>(y + (size_t)row * K)[tid] = o4;
}

extern "C" void kernel_launch(void* const* d_in, const int* in_sizes, int n_in,
                              void* d_out, int out_size)
{
    const float* x = (const float*)d_in[0];
    float*       y = (float*)d_out;
    const int rows = out_size / K;   // 8 * 1024 = 8192 for the bench shape
    sparsemax_rowwise_kernel<<<rows, THREADS>>>(x, y);
}

// round 2
// speedup vs baseline: 1.6808x; 1.6808x over previous
#include <cuda_runtime.h>
#include <cstdint>
#include <math_constants.h>

// Sparsemax (faithful-to-buggy-reference): per contiguous row of K=2048:
//   r = inclusive cumsum(z); unmasked_k: 1 + k*z_k > r_k (1-indexed)
//   kmax = max unmasked k; tmax = max unmasked r_k
//   tau = (tmax-1)/kmax; out = max(0, z - tau)
//
// One CTA (256 threads, 8 warps) per row, 8 elems/thread (2x float4).
// Cross-warp scan + final reduction delegated to warp 0 (log-step shuffles)
// so the other 248 threads pay only broadcast LDS, not serial loops.

constexpr int K       = 2048;
constexpr int THREADS = 256;
constexpr int EPT     = 8;            // elements per thread
constexpr int NW      = THREADS / 32; // 8 warps

__global__ __launch_bounds__(THREADS, 5)
void sparsemax_rowwise_kernel(const float* __restrict__ x, float* __restrict__ y)
{
    const int row  = blockIdx.x;
    const int tid  = threadIdx.x;
    const int lane = tid & 31;
    const int wid  = tid >> 5;

    const float4* __restrict__ xin =
        reinterpret_cast<const float4*>(x + (size_t)row * K);
    float4 a = __ldcs(xin + tid * 2);
    float4 b = __ldcs(xin + tid * 2 + 1);

    float z[EPT] = {a.x, a.y, a.z, a.w, b.x, b.y, b.z, b.w};

    // Thread-local inclusive prefix
    float s[EPT];
    s[0] = z[0];
    #pragma unroll
    for (int i = 1; i < EPT; i++) s[i] = s[i - 1] + z[i];

    // Warp inclusive scan of per-thread sums
    float sc = s[EPT - 1];
    #pragma unroll
    for (int o = 1; o < 32; o <<= 1) {
        float t = __shfl_up_sync(0xffffffffu, sc, o);
        if (lane >= o) sc += t;
    }

    __shared__ float wsum[NW], woff[NW], wk[NW], wt[NW];
    __shared__ float stau;

    if (lane == 31) wsum[wid] = sc;
    __syncthreads();

    // Warp 0 (lanes 0..7): exclusive scan across the 8 warp sums
    if (tid < NW) {
        float v   = wsum[tid];
        float inc = v;
        #pragma unroll
        for (int o = 1; o < NW; o <<= 1) {
            float t = __shfl_up_sync(0x000000ffu, inc, o);
            if (tid >= o) inc += t;
        }
        woff[tid] = inc - v;
    }
    __syncthreads();

    const float base = woff[wid] + (sc - s[EPT - 1]);

    // Per-element mask + running maxes. k (1-indexed) = tid*EPT + i + 1.
    const float kb = (float)(tid * EPT);
    float kmax = 0.0f;
    float tmax = -CUDART_INF_F;
    #pragma unroll
    for (int i = 0; i < EPT; i++) {
        const float r  = base + s[i];
        const float kk = kb + (float)(i + 1);
        if (fmaf(kk, z[i], 1.0f) > r) {
            kmax = fmaxf(kmax, kk);
            tmax = fmaxf(tmax, r);
        }
    }

    // Warp max reductions
    #pragma unroll
    for (int o = 16; o >= 1; o >>= 1) {
        kmax = fmaxf(kmax, __shfl_xor_sync(0xffffffffu, kmax, o));
        tmax = fmaxf(tmax, __shfl_xor_sync(0xffffffffu, tmax, o));
    }
    if (lane == 0) { wk[wid] = kmax; wt[wid] = tmax; }
    __syncthreads();

    // Warp 0 reduces the 8 per-warp maxes, computes tau once
    if (tid < NW) {
        float km = wk[tid], tm = wt[tid];
        #pragma unroll
        for (int o = NW / 2; o >= 1; o >>= 1) {
            km = fmaxf(km, __shfl_xor_sync(0x000000ffu, km, o));
            tm = fmaxf(tm, __shfl_xor_sync(0x000000ffu, tm, o));
        }
        if (tid == 0) stau = __fdividef(tm - 1.0f, km);
    }
    __syncthreads();

    const float tau = stau;

    float4 o1, o2;
    o1.x = fmaxf(0.0f, z[0] - tau);
    o1.y = fmaxf(0.0f, z[1] - tau);
    o1.z = fmaxf(0.0f, z[2] - tau);
    o1.w = fmaxf(0.0f, z[3] - tau);
    o2.x = fmaxf(0.0f, z[4] - tau);
    o2.y = fmaxf(0.0f, z[5] - tau);
    o2.z = fmaxf(0.0f, z[6] - tau);
    o2.w = fmaxf(0.0f, z[7] - tau);

    float4* __restrict__ yout = reinterpret_cast<float4*>(y + (size_t)row * K);
    __stcs(yout + tid * 2,     o1);
    __stcs(yout + tid * 2 + 1, o2);
}

extern "C" void kernel_launch(void* const* d_in, const int* in_sizes, int n_in,
                              void* d_out, int out_size)
{
    const float* x = (const float*)d_in[0];
    float*       y = (float*)d_out;
    const int rows = out_size / K;   // 8192 for the bench shape
    sparsemax_rowwise_kernel<<<rows, THREADS>>>(x, y);
}

// round 3
// speedup vs baseline: 1.8592x; 1.1061x over previous
#include <cuda_runtime.h>
#include <cstdint>
#include <math_constants.h>

// Sparsemax (faithful-to-buggy-reference): per contiguous row of K=2048:
//   r = inclusive cumsum(z); unmasked_k: 1 + k*z_k > r_k (1-indexed)
//   kmax = max unmasked k; tmax = max unmasked r_k
//   tau = (tmax-1)/kmax; out = max(0, z - tau)
//
// One CTA (128 threads, 4 warps) per row, 16 contiguous elems/thread.
// Thread total via pairwise tree; running prefix regenerated in the mask
// loop (no s[] array). Warp maxes via REDUX.SYNC.MAX.U32 (float-ordered
// uint map for tmax). Two __syncthreads total; cross-warp combine inlined
// in every thread (only 4 warps).

constexpr int K       = 2048;
constexpr int THREADS = 128;
constexpr int EPT     = 16;
constexpr int NW      = THREADS / 32;   // 4 warps

__device__ __forceinline__ unsigned f2ord(float f) {
    unsigned u = __float_as_uint(f);
    return (u & 0x80000000u) ? ~u : (u | 0x80000000u);
}
__device__ __forceinline__ float ord2f(unsigned u) {
    return __uint_as_float((u & 0x80000000u) ? (u ^ 0x80000000u) : ~u);
}

__global__ __launch_bounds__(THREADS)
void sparsemax_rowwise_kernel(const float* __restrict__ x, float* __restrict__ y)
{
    const int row  = blockIdx.x;
    const int tid  = threadIdx.x;
    const int lane = tid & 31;
    const int wid  = tid >> 5;

    const float4* __restrict__ xin =
        reinterpret_cast<const float4*>(x + (size_t)row * K) + tid * 4;
    float4 v0 = __ldcs(xin + 0);
    float4 v1 = __ldcs(xin + 1);
    float4 v2 = __ldcs(xin + 2);
    float4 v3 = __ldcs(xin + 3);

    float z[EPT] = {v0.x, v0.y, v0.z, v0.w,  v1.x, v1.y, v1.z, v1.w,
                    v2.x, v2.y, v2.z, v2.w,  v3.x, v3.y, v3.z, v3.w};

    // Thread total via pairwise tree (short dependency chain)
    float p0 = (z[0]  + z[1])  + (z[2]  + z[3]);
    float p1 = (z[4]  + z[5])  + (z[6]  + z[7]);
    float p2 = (z[8]  + z[9])  + (z[10] + z[11]);
    float p3 = (z[12] + z[13]) + (z[14] + z[15]);
    const float tot = (p0 + p1) + (p2 + p3);

    // Warp inclusive scan of per-thread totals
    float sc = tot;
    #pragma unroll
    for (int o = 1; o < 32; o <<= 1) {
        float t = __shfl_up_sync(0xffffffffu, sc, o);
        if (lane >= o) sc += t;
    }

    __shared__ float    wsum[NW];
    __shared__ unsigned wk[NW], wt[NW];

    if (lane == 31) wsum[wid] = sc;
    __syncthreads();

    // Inline cross-warp exclusive offset (4 entries, broadcast LDS)
    float woff = 0.0f;
    #pragma unroll
    for (int i = 0; i < NW; i++) {
        float t = wsum[i];
        if (i < wid) woff += t;
    }

    // Running inclusive prefix, regenerated element-by-element
    float run = woff + (sc - tot);
    const float kb = (float)(tid * EPT);
    float kmax = 0.0f;
    float tmax = -CUDART_INF_F;
    #pragma unroll
    for (int i = 0; i < EPT; i++) {
        run += z[i];
        const float kk = kb + (float)(i + 1);
        if (fmaf(kk, z[i], 1.0f) > run) {
            kmax = fmaxf(kmax, kk);
            tmax = fmaxf(tmax, run);
        }
    }

    // Warp max reductions via REDUX (kmax is an exact small integer)
    unsigned ku = __float2uint_rz(kmax);
    unsigned tu = f2ord(tmax);
    ku = __reduce_max_sync(0xffffffffu, ku);
    tu = __reduce_max_sync(0xffffffffu, tu);

    if (lane == 0) { wk[wid] = ku; wt[wid] = tu; }
    __syncthreads();

    // Inline cross-warp max (4+4 broadcast LDS), tau per-thread
    unsigned km = wk[0], tm = wt[0];
    #pragma unroll
    for (int i = 1; i < NW; i++) {
        km = max(km, wk[i]);
        tm = max(tm, wt[i]);
    }
    const float tau = __fdividef(ord2f(tm) - 1.0f, __uint2float_rn(km));

    float4 o0, o1, o2, o3;
    o0.x = fmaxf(0.0f, z[0]  - tau);  o0.y = fmaxf(0.0f, z[1]  - tau);
    o0.z = fmaxf(0.0f, z[2]  - tau);  o0.w = fmaxf(0.0f, z[3]  - tau);
    o1.x = fmaxf(0.0f, z[4]  - tau);  o1.y = fmaxf(0.0f, z[5]  - tau);
    o1.z = fmaxf(0.0f, z[6]  - tau);  o1.w = fmaxf(0.0f, z[7]  - tau);
    o2.x = fmaxf(0.0f, z[8]  - tau);  o2.y = fmaxf(0.0f, z[9]  - tau);
    o2.z = fmaxf(0.0f, z[10] - tau);  o2.w = fmaxf(0.0f, z[11] - tau);
    o3.x = fmaxf(0.0f, z[12] - tau);  o3.y = fmaxf(0.0f, z[13] - tau);
    o3.z = fmaxf(0.0f, z[14] - tau);  o3.w = fmaxf(0.0f, z[15] - tau);

    float4* __restrict__ yout =
        reinterpret_cast<float4*>(y + (size_t)row * K) + tid * 4;
    __stcs(yout + 0, o0);
    __stcs(yout + 1, o1);
    __stcs(yout + 2, o2);
    __stcs(yout + 3, o3);
}

extern "C" void kernel_launch(void* const* d_in, const int* in_sizes, int n_in,
                              void* d_out, int out_size)
{
    const float* x = (const float*)d_in[0];
    float*       y = (float*)d_out;
    const int rows = out_size / K;   // 8192 for the bench shape
    sparsemax_rowwise_kernel<<<rows, THREADS>>>(x, y);
}